// round 2
// baseline (speedup 1.0000x reference)
#include <cuda_runtime.h>
#include <cfloat>
#include <math.h>

#define B_   32
#define T_   512
#define DIN  1024
#define DCB  256
#define KCB  8192
#define HMID 512
#define M_   (B_*T_)   // 16384
#define K3   (3*DCB)   // 768

// ---------------- scratch (static __device__ — no runtime allocation) ----------
__device__ float g_Y1[M_*HMID];
__device__ float g_Y2[M_*DCB];
__device__ float g_A3[M_*K3];
__device__ float g_Wc[DCB*K3];
__device__ float g_feat[M_*DCB];
__device__ float g_cnorm[KCB];
__device__ float g_rownorm[M_];
__device__ float g_pval[M_*4];
__device__ int   g_pidx[M_*4];
__device__ int   g_idx[M_];
__device__ float g_quant[M_*DCB];
__device__ float g_xproj[M_*K3];
__device__ float g_whhT[DCB*K3];
__device__ float g_accum[2];

// ---------------- generic fp32 SIMT GEMM:  C = act(A[M,K] @ B[N,K]^T + bias) ----
// Accumulation: single accumulator, ascending-k fused-multiply-add chain
// (bit-matches Eigen gebp per-output accumulation).
#define BM 128
#define BN 128
#define BKK 16
#define TM 8
#define TN 8

template<int RELU>
__global__ __launch_bounds__(256) void gemm_tn(
    const float* __restrict__ A, const float* __restrict__ B,
    const float* __restrict__ bias, float* __restrict__ C,
    int M, int N, int K)
{
    __shared__ float As[BKK][BM+4];
    __shared__ float Bs[BKK][BN+4];
    int tid = threadIdx.x;
    int tr = tid >> 4, tc = tid & 15;
    int m0 = blockIdx.y * BM, n0 = blockIdx.x * BN;
    float acc[TM][TN];
    #pragma unroll
    for (int i = 0; i < TM; i++)
        #pragma unroll
        for (int j = 0; j < TN; j++) acc[i][j] = 0.f;

    for (int k0 = 0; k0 < K; k0 += BKK) {
        #pragma unroll
        for (int it = 0; it < 2; it++) {
            int id = tid + it*256;          // 0..511
            int row = id >> 2;              // 0..127
            int kq  = (id & 3) << 2;        // 0,4,8,12
            float4 v = *(const float4*)&A[(size_t)(m0+row)*K + k0 + kq];
            As[kq+0][row] = v.x; As[kq+1][row] = v.y;
            As[kq+2][row] = v.z; As[kq+3][row] = v.w;
        }
        #pragma unroll
        for (int it = 0; it < 2; it++) {
            int id = tid + it*256;
            int row = id >> 2;
            int kq  = (id & 3) << 2;
            float4 v = *(const float4*)&B[(size_t)(n0+row)*K + k0 + kq];
            Bs[kq+0][row] = v.x; Bs[kq+1][row] = v.y;
            Bs[kq+2][row] = v.z; Bs[kq+3][row] = v.w;
        }
        __syncthreads();
        #pragma unroll
        for (int kk = 0; kk < BKK; kk++) {
            float ra[TM], rb[TN];
            #pragma unroll
            for (int i = 0; i < TM; i++) ra[i] = As[kk][tr*TM+i];
            #pragma unroll
            for (int j = 0; j < TN; j++) rb[j] = Bs[kk][tc*TN+j];
            #pragma unroll
            for (int i = 0; i < TM; i++)
                #pragma unroll
                for (int j = 0; j < TN; j++)
                    acc[i][j] = __fmaf_rn(ra[i], rb[j], acc[i][j]);
        }
        __syncthreads();
    }
    #pragma unroll
    for (int i = 0; i < TM; i++) {
        int m = m0 + tr*TM + i;
        #pragma unroll
        for (int j = 0; j < TN; j++) {
            int n = n0 + tc*TN + j;
            float v = __fadd_rn(acc[i][j], bias[n]);
            if (RELU) v = fmaxf(v, 0.f);
            C[(size_t)m*N + n] = v;
        }
    }
}

// ---------------- small prep kernels ------------------------------------------
__global__ void zero_accums() { if (threadIdx.x < 2) g_accum[threadIdx.x] = 0.f; }

__global__ void prep_wc(const float* __restrict__ conv_w) {
    int o = blockIdx.x*blockDim.x + threadIdx.x;   // < 256*768
    if (o >= DCB*K3) return;
    int c = o / K3, r = o % K3, k = r / DCB, i = r % DCB;
    g_Wc[o] = conv_w[((size_t)c*DCB + i)*3 + k];
}

__global__ void transpose_whh(const float* __restrict__ whh) {
    int o = blockIdx.x*blockDim.x + threadIdx.x;   // < 256*768
    if (o >= DCB*K3) return;
    int d = o / K3, j = o % K3;
    g_whhT[o] = whh[(size_t)j*DCB + d];
}

__global__ void im2col_k() {
    int stride = gridDim.x * blockDim.x;
    for (int o = blockIdx.x*blockDim.x + threadIdx.x; o < M_*K3; o += stride) {
        int m = o / K3, r = o % K3, k = r / DCB, i = r % DCB;
        int b = m >> 9, t = m & 511;
        int tt = t + k - 1;
        g_A3[o] = (tt >= 0 && tt < T_) ? g_Y2[((size_t)(b*T_ + tt))*DCB + i] : 0.f;
    }
}

// sequential scalar sum of squares: a += fl(v*v)  (mul then add, no FMA) —
// replicates XLA:CPU's scalar reduce emission bit-for-bit.
__global__ void cnorm_k(const float* __restrict__ CB) {
    int k = blockIdx.x*blockDim.x + threadIdx.x;
    if (k >= KCB) return;
    const float* row = CB + (size_t)k*DCB;
    float a = 0.f;
    for (int d = 0; d < DCB; d++) {
        float v = row[d];
        a = __fadd_rn(a, __fmul_rn(v, v));
    }
    g_cnorm[k] = a;
}

__global__ void rownorm_k() {
    int m = blockIdx.x*blockDim.x + threadIdx.x;
    if (m >= M_) return;
    const float* row = g_feat + (size_t)m*DCB;
    float a = 0.f;
    for (int d = 0; d < DCB; d++) {
        float v = row[d];
        a = __fadd_rn(a, __fmul_rn(v, v));
    }
    g_rownorm[m] = a;
}

// ---------------- fused VQ distance GEMM + argmin ------------------------------
// d2 = fl( fl(A - 2*P) + C )  — exact replication of the reference's
// (|f|^2 - 2 f.c) + |c|^2 fp32 rounding sequence (2*P is exact).
// grid = (4 k-splits, M/128). Each block: 128 feature rows x 2048 codebook rows.
__global__ __launch_bounds__(256) void vq_argmin(
    const float* __restrict__ F, const float* __restrict__ CB)
{
    __shared__ float As[BKK][BM+4];
    __shared__ float Bs[BKK][BN+4];
    __shared__ float sv[128][16];
    __shared__ int   si[128][16];
    int tid = threadIdx.x;
    int tr = tid >> 4, tc = tid & 15;
    int m0 = blockIdx.y * BM;
    int kbase = blockIdx.x * 2048;

    float Arow[TM];
    #pragma unroll
    for (int i = 0; i < TM; i++) Arow[i] = g_rownorm[m0 + tr*TM + i];

    float bestv[TM]; int besti[TM];
    #pragma unroll
    for (int i = 0; i < TM; i++) { bestv[i] = FLT_MAX; besti[i] = 0x7fffffff; }

    for (int ct = 0; ct < 16; ct++) {
        int n0 = kbase + ct*128;
        float acc[TM][TN];
        #pragma unroll
        for (int i = 0; i < TM; i++)
            #pragma unroll
            for (int j = 0; j < TN; j++) acc[i][j] = 0.f;

        for (int k0 = 0; k0 < DCB; k0 += BKK) {
            #pragma unroll
            for (int it = 0; it < 2; it++) {
                int id = tid + it*256;
                int row = id >> 2;
                int kq = (id & 3) << 2;
                float4 v = *(const float4*)&F[(size_t)(m0+row)*DCB + k0 + kq];
                As[kq+0][row] = v.x; As[kq+1][row] = v.y;
                As[kq+2][row] = v.z; As[kq+3][row] = v.w;
            }
            #pragma unroll
            for (int it = 0; it < 2; it++) {
                int id = tid + it*256;
                int row = id >> 2;
                int kq = (id & 3) << 2;
                float4 v = *(const float4*)&CB[(size_t)(n0+row)*DCB + k0 + kq];
                Bs[kq+0][row] = v.x; Bs[kq+1][row] = v.y;
                Bs[kq+2][row] = v.z; Bs[kq+3][row] = v.w;
            }
            __syncthreads();
            #pragma unroll
            for (int kk = 0; kk < BKK; kk++) {
                float ra[TM], rb[TN];
                #pragma unroll
                for (int i = 0; i < TM; i++) ra[i] = As[kk][tr*TM+i];
                #pragma unroll
                for (int j = 0; j < TN; j++) rb[j] = Bs[kk][tc*TN+j];
                #pragma unroll
                for (int i = 0; i < TM; i++)
                    #pragma unroll
                    for (int j = 0; j < TN; j++)
                        acc[i][j] = __fmaf_rn(ra[i], rb[j], acc[i][j]);
            }
            __syncthreads();
        }
        // epilogue: s = fl(fl(A - 2P) + C) ; lexicographic (val, idx) min
        #pragma unroll
        for (int j = 0; j < TN; j++) {
            int kidx = n0 + tc*TN + j;
            float cn = g_cnorm[kidx];
            #pragma unroll
            for (int i = 0; i < TM; i++) {
                float twoP = __fmul_rn(2.0f, acc[i][j]);   // exact
                float s1 = __fadd_rn(Arow[i], -twoP);
                float s  = __fadd_rn(s1, cn);
                if (s < bestv[i] || (s == bestv[i] && kidx < besti[i])) {
                    bestv[i] = s; besti[i] = kidx;
                }
            }
        }
    }
    // reduce across the 16 threads sharing each row
    #pragma unroll
    for (int i = 0; i < TM; i++) { sv[tr*TM+i][tc] = bestv[i]; si[tr*TM+i][tc] = besti[i]; }
    __syncthreads();
    if (tid < 128) {
        float bv = FLT_MAX; int bi = 0x7fffffff;
        #pragma unroll
        for (int t = 0; t < 16; t++) {
            float v = sv[tid][t]; int ix = si[tid][t];
            if (v < bv || (v == bv && ix < bi)) { bv = v; bi = ix; }
        }
        g_pval[(size_t)(m0+tid)*4 + blockIdx.x] = bv;
        g_pidx[(size_t)(m0+tid)*4 + blockIdx.x] = bi;
    }
}

__global__ void vq_reduce(float* __restrict__ out) {
    int m = blockIdx.x*blockDim.x + threadIdx.x;
    if (m >= M_) return;
    float bv = g_pval[m*4]; int bi = g_pidx[m*4];
    #pragma unroll
    for (int s = 1; s < 4; s++) {
        float v = g_pval[m*4+s]; int ix = g_pidx[m*4+s];
        if (v < bv || (v == bv && ix < bi)) { bv = v; bi = ix; }
    }
    g_idx[m] = bi;
    out[m] = (float)bi;   // token_indices as float
}

// gather quantized, write to out, accumulate sum((feat-quant)^2)
__global__ void quant_mse(const float* __restrict__ CB, float* __restrict__ out) {
    int m = blockIdx.x, c = threadIdx.x;
    int id = g_idx[m];
    float q = CB[(size_t)id*DCB + c];
    g_quant[(size_t)m*DCB + c] = q;
    out[M_ + (size_t)m*DCB + c] = q;
    float d = g_feat[(size_t)m*DCB + c] - q;
    float s = d*d;
    #pragma unroll
    for (int off = 16; off; off >>= 1) s += __shfl_down_sync(0xffffffffu, s, off);
    __shared__ float red[8];
    if ((c & 31) == 0) red[c >> 5] = s;
    __syncthreads();
    if (c == 0) {
        float t = 0.f;
        #pragma unroll
        for (int w = 0; w < 8; w++) t += red[w];
        atomicAdd(&g_accum[0], t);
    }
}

// ---------------- GRU: 32 blocks (one per batch), 768 threads ------------------
__global__ __launch_bounds__(768) void gru_kernel(const float* __restrict__ bhh) {
    int b = blockIdx.x;
    int tid = threadIdx.x;
    int ds = tid / 192;          // 0..3 : d-range [ds*64, ds*64+64)
    int jj = tid % 192;          // outputs 4*jj .. 4*jj+3
    __shared__ float sh_h[DCB];
    __shared__ float sh_gh[K3];
    __shared__ float part[4][K3];
    if (tid < DCB) sh_h[tid] = 0.f;
    float bv0=0,bv1=0,bv2=0,bv3=0;
    if (ds == 0) { bv0=bhh[jj*4]; bv1=bhh[jj*4+1]; bv2=bhh[jj*4+2]; bv3=bhh[jj*4+3]; }
    const float* wbase = g_whhT + (size_t)(ds*64)*K3 + jj*4;
    float ctxsum = 0.f;
    __syncthreads();

    for (int t = 0; t < T_-1; t++) {
        float ax=0.f, ay=0.f, az=0.f, aw=0.f;
        const float* wp = wbase;
        const float* hp = sh_h + ds*64;
        #pragma unroll 8
        for (int d = 0; d < 64; d++) {
            float hv = hp[d];
            float4 w = *(const float4*)wp;
            ax = fmaf(hv, w.x, ax); ay = fmaf(hv, w.y, ay);
            az = fmaf(hv, w.z, az); aw = fmaf(hv, w.w, aw);
            wp += K3;
        }
        part[ds][jj*4+0]=ax; part[ds][jj*4+1]=ay; part[ds][jj*4+2]=az; part[ds][jj*4+3]=aw;
        __syncthreads();
        if (ds == 0) {
            int o = jj*4;
            sh_gh[o+0] = part[0][o+0]+part[1][o+0]+part[2][o+0]+part[3][o+0] + bv0;
            sh_gh[o+1] = part[0][o+1]+part[1][o+1]+part[2][o+1]+part[3][o+1] + bv1;
            sh_gh[o+2] = part[0][o+2]+part[1][o+2]+part[2][o+2]+part[3][o+2] + bv2;
            sh_gh[o+3] = part[0][o+3]+part[1][o+3]+part[2][o+3]+part[3][o+3] + bv3;
        }
        __syncthreads();
        if (tid < DCB) {
            int j = tid;
            const float* xp = g_xproj + ((size_t)b*T_ + t)*K3;
            float r = 1.f/(1.f + expf(-(xp[j]       + sh_gh[j])));
            float z = 1.f/(1.f + expf(-(xp[DCB+j]   + sh_gh[DCB+j])));
            float n = tanhf(xp[2*DCB+j] + r*sh_gh[2*DCB+j]);
            float hprev = sh_h[j];
            float hnew = (1.f - z)*n + z*hprev;
            float dl = hnew - g_feat[((size_t)b*T_ + t + 1)*DCB + j];
            ctxsum = fmaf(dl, dl, ctxsum);
            sh_h[j] = hnew;
        }
        __syncthreads();
    }
    #pragma unroll
    for (int off = 16; off; off >>= 1) ctxsum += __shfl_down_sync(0xffffffffu, ctxsum, off);
    __shared__ float wsum[24];
    if ((tid & 31) == 0) wsum[tid >> 5] = ctxsum;
    __syncthreads();
    if (tid == 0) {
        float s = 0.f;
        #pragma unroll
        for (int w = 0; w < 24; w++) s += wsum[w];
        atomicAdd(&g_accum[1], s);
    }
}

__global__ void finalize_k(float* __restrict__ out) {
    float mse = g_accum[0] / 4194304.0f;              // 16384*256
    float ctx = g_accum[1] / 4186112.0f;              // 32*511*256
    size_t base = (size_t)M_ + (size_t)M_*DCB;        // 4210688
    out[base+0] = mse;                                // commitment_loss
    out[base+1] = mse;                                // codebook_loss (identical expr)
    out[base+2] = ctx;                                // context_loss
    out[base+3] = 1.25f*mse + 0.1f*ctx;               // vq_loss
}

// ---------------- launch --------------------------------------------------------
extern "C" void kernel_launch(void* const* d_in, const int* in_sizes, int n_in,
                              void* d_out, int out_size) {
    const float* x      = (const float*)d_in[0];
    const float* w1     = (const float*)d_in[1];
    const float* b1     = (const float*)d_in[2];
    const float* w2     = (const float*)d_in[3];
    const float* b2     = (const float*)d_in[4];
    const float* conv_w = (const float*)d_in[5];
    const float* conv_b = (const float*)d_in[6];
    const float* cb     = (const float*)d_in[7];
    const float* wih    = (const float*)d_in[8];
    const float* whh    = (const float*)d_in[9];
    const float* bih    = (const float*)d_in[10];
    const float* bhh    = (const float*)d_in[11];
    float* out = (float*)d_out;

    float *pY1, *pY2, *pA3, *pWc, *pF, *pQ, *pXp;
    cudaGetSymbolAddress((void**)&pY1, g_Y1);
    cudaGetSymbolAddress((void**)&pY2, g_Y2);
    cudaGetSymbolAddress((void**)&pA3, g_A3);
    cudaGetSymbolAddress((void**)&pWc, g_Wc);
    cudaGetSymbolAddress((void**)&pF,  g_feat);
    cudaGetSymbolAddress((void**)&pQ,  g_quant);
    cudaGetSymbolAddress((void**)&pXp, g_xproj);

    zero_accums<<<1, 32>>>();

    gemm_tn<1><<<dim3(HMID/BN, M_/BM), 256>>>(x,   w1, b1, pY1, M_, HMID, DIN);
    gemm_tn<1><<<dim3(DCB/BN,  M_/BM), 256>>>(pY1, w2, b2, pY2, M_, DCB, HMID);

    prep_wc<<<(DCB*K3+255)/256, 256>>>(conv_w);
    im2col_k<<<4096, 256>>>();
    gemm_tn<0><<<dim3(DCB/BN, M_/BM), 256>>>(pA3, pWc, conv_b, pF, M_, DCB, K3);

    cnorm_k<<<KCB/256, 256>>>(cb);
    rownorm_k<<<M_/256, 256>>>();
    vq_argmin<<<dim3(4, M_/BM), 256>>>(pF, cb);
    vq_reduce<<<M_/256, 256>>>(out);
    quant_mse<<<M_, 256>>>(cb, out);

    gemm_tn<0><<<dim3(K3/BN, M_/BM), 256>>>(pQ, wih, bih, pXp, M_, K3, DCB);
    transpose_whh<<<(DCB*K3+255)/256, 256>>>(whh);
    gru_kernel<<<B_, 768>>>(bhh);

    finalize_k<<<1, 1>>>(out);
}